// round 8
// baseline (speedup 1.0000x reference)
#include <cuda_runtime.h>

// ---------------------------------------------------------------------------
// DecoderBlock: conv3x3(64->3) + bias + tanh  -> ll [16,3,128,128]
// then two fused inverse Haar levels          -> out [16,3,512,512]
//
// R8: R7 split-K conv shape + packed fma.rn.f32x2 inner loop.
//     Combine + bias + tanh stays fused in iwt2.
// ---------------------------------------------------------------------------

#define NB   16
#define CIN  64
#define KSPLIT 2
#define KCH  (CIN / KSPLIT)     // 32 channels per CTA
#define HH   128
#define WW   128
#define HW   (HH * WW)

// partial conv sums: [kslice][b][o][h][w] = 2 * 3 MB
__device__ float g_part[KSPLIT * NB * 3 * HW];

typedef unsigned long long ull;

__device__ __forceinline__ ull pack2(float lo, float hi) {
    ull r;
    asm("mov.b64 %0, {%1, %2};" : "=l"(r) : "f"(lo), "f"(hi));
    return r;
}
__device__ __forceinline__ void unpack2(ull v, float& lo, float& hi) {
    asm("mov.b64 {%0, %1}, %2;" : "=f"(lo), "=f"(hi) : "l"(v));
}
// packed dual-fp32 FMA (sm_100+): d = a*b+c on both 32-bit halves
__device__ __forceinline__ ull fma2(ull a, ull b, ull c) {
    ull d;
    asm("fma.rn.f32x2 %0, %1, %2, %3;" : "=l"(d) : "l"(a), "l"(b), "l"(c));
    return d;
}

// ---------------------------------------------------------------------------
// Kernel A: streaming conv 3x3 pad1, split-K partials, f32x2 math.
// Thread = 1 row x 4 cols x 3 outch (2 packed accumulators per outch).
// CTA (32,4)=128 thr covers 128x4 band. Grid (32,16,2) = 1024 CTAs.
// Weights pre-duplicated {w,w} in smem: [c][o][10 ull] (9 used, 16B strides).
// ---------------------------------------------------------------------------
__global__ __launch_bounds__(128) void conv_part_kernel(
    const float* __restrict__ fused,
    const float* __restrict__ conv_w)
{
    __shared__ ull s_w[KCH * 30];             // 7680 B

    const int tx  = threadIdx.x;              // 0..31 -> cols 4tx..4tx+3
    const int ty  = threadIdx.y;              // 0..3
    const int tid = ty * 32 + tx;
    const int b   = blockIdx.y;
    const int ks  = blockIdx.z;               // k-slice 0/1
    const int kbase = ks * KCH;
    const int gy  = blockIdx.x * 4 + ty;      // output row 0..127

    // stage packed weights: s_w[c*30 + o*10 + t] = {w,w}
    for (int i = tid; i < KCH * 27; i += 128) {
        int c = i / 27, r = i % 27;
        float w = conv_w[(r / 9) * (CIN * 9) + (kbase + c) * 9 + (r % 9)];
        s_w[c * 30 + (r / 9) * 10 + (r % 9)] = pack2(w, w);
    }
    __syncthreads();

    const bool vtop = (gy > 0);
    const bool vbot = (gy < HH - 1);
    const bool vl   = (tx > 0);
    const bool vr   = (tx < 31);
    const float* p0 = fused + (long)b * CIN * HW + (long)kbase * HW
                            + (gy - 1) * WW + 4 * tx;

    float x0[3][6], x1[3][6];

    auto loadch = [&](int c, float (&x)[3][6]) {
        const bool rv[3] = { vtop, true, vbot };
#pragma unroll
        for (int k = 0; k < 3; k++) {
            const float* rp = p0 + c * HW + k * WW;
            float4 m = make_float4(0.f, 0.f, 0.f, 0.f);
            float l = 0.f, r = 0.f;
            if (rv[k]) {
                m = __ldg(reinterpret_cast<const float4*>(rp));
                if (vl) l = __ldg(rp - 1);
                if (vr) r = __ldg(rp + 4);
            }
            x[k][0] = l;   x[k][1] = m.x; x[k][2] = m.y;
            x[k][3] = m.z; x[k][4] = m.w; x[k][5] = r;
        }
    };

    // packed accumulators: accA = cols {0,1}, accB = cols {2,3}
    ull accA[3], accB[3];
#pragma unroll
    for (int o = 0; o < 3; o++) { accA[o] = pack2(0.f, 0.f); accB[o] = accA[o]; }

    auto compute = [&](int c, float (&x)[3][6]) {
        // packed input pairs per row: (x_j, x_{j+1}) for j=0..4
        ull xs[3][5];
#pragma unroll
        for (int k = 0; k < 3; k++)
#pragma unroll
            for (int j = 0; j < 5; j++)
                xs[k][j] = pack2(x[k][j], x[k][j + 1]);

        const ulonglong2* wp2 =
            reinterpret_cast<const ulonglong2*>(&s_w[c * 30]);
#pragma unroll
        for (int o = 0; o < 3; o++) {
            // 9 packed weights via 5 LDS.128 (broadcast)
            ulonglong2 q0 = wp2[o * 5 + 0];
            ulonglong2 q1 = wp2[o * 5 + 1];
            ulonglong2 q2 = wp2[o * 5 + 2];
            ulonglong2 q3 = wp2[o * 5 + 3];
            ulonglong2 q4 = wp2[o * 5 + 4];
            ull w0 = q0.x, w1 = q0.y, w2 = q1.x,
                w3 = q1.y, w4 = q2.x, w5 = q2.y,
                w6 = q3.x, w7 = q3.y, w8 = q4.x;
            ull a = accA[o], bacc = accB[o];
            a = fma2(w0, xs[0][0], a);  bacc = fma2(w0, xs[0][2], bacc);
            a = fma2(w1, xs[0][1], a);  bacc = fma2(w1, xs[0][3], bacc);
            a = fma2(w2, xs[0][2], a);  bacc = fma2(w2, xs[0][4], bacc);
            a = fma2(w3, xs[1][0], a);  bacc = fma2(w3, xs[1][2], bacc);
            a = fma2(w4, xs[1][1], a);  bacc = fma2(w4, xs[1][3], bacc);
            a = fma2(w5, xs[1][2], a);  bacc = fma2(w5, xs[1][4], bacc);
            a = fma2(w6, xs[2][0], a);  bacc = fma2(w6, xs[2][2], bacc);
            a = fma2(w7, xs[2][1], a);  bacc = fma2(w7, xs[2][3], bacc);
            a = fma2(w8, xs[2][2], a);  bacc = fma2(w8, xs[2][4], bacc);
            accA[o] = a; accB[o] = bacc;
        }
    };

    loadch(0, x0);
#pragma unroll 1
    for (int c = 0; c < KCH; c += 2) {
        loadch(c + 1, x1);
        compute(c, x0);
        if (c + 2 < KCH) loadch(c + 2, x0);
        compute(c + 1, x1);
    }

    // raw partial sums, one float4 per out channel
    float* pp = &g_part[(long)ks * NB * 3 * HW];
#pragma unroll
    for (int o = 0; o < 3; o++) {
        float4 v;
        unpack2(accA[o], v.x, v.y);
        unpack2(accB[o], v.z, v.w);
        *reinterpret_cast<float4*>(
            &pp[((b * 3 + o) * HH + gy) * WW + 4 * tx]) = v;
    }
}

// ---------------------------------------------------------------------------
// Kernel B: combine(partials)+bias+tanh fused with double inverse Haar.
// ---------------------------------------------------------------------------
__global__ __launch_bounds__(256) void iwt2_kernel(
    const float* __restrict__ hf1,
    const float* __restrict__ hf2,
    const float* __restrict__ conv_b,
    float* __restrict__ out)
{
    const int w0 = threadIdx.x;                        // 0..127
    const int h0 = blockIdx.x * 2 + threadIdx.y;       // 0..127
    const int z  = blockIdx.y;                         // b*3 + c
    const int b  = z / 3;
    const int c  = z - b * 3;

    const int llidx = (z * HH + h0) * WW + w0;
    const float a = tanhf(g_part[llidx] + g_part[NB * 3 * HW + llidx]
                          + __ldg(&conv_b[c]));

    const int hf2base = ((b * 9 + 3 * c) * HH + h0) * WW + w0;
    const float lh = 2.0f * __ldg(&hf2[hf2base            ]) - 1.0f;
    const float hl = 2.0f * __ldg(&hf2[hf2base + HH * WW  ]) - 1.0f;
    const float hh = 2.0f * __ldg(&hf2[hf2base + 2*HH*WW  ]) - 1.0f;

    float cur[2][2];
    cur[0][0] = 0.5f * (a - lh - hl + hh);
    cur[0][1] = 0.5f * (a - lh + hl - hh);
    cur[1][0] = 0.5f * (a + lh - hl - hh);
    cur[1][1] = 0.5f * (a + lh + hl + hh);

    const int h1 = 2 * h0;
    const int w1 = 2 * w0;
    float2 v[3][2];
#pragma unroll
    for (int k = 0; k < 3; k++) {
#pragma unroll
        for (int p0 = 0; p0 < 2; p0++) {
            const float2* ptr = reinterpret_cast<const float2*>(
                &hf1[((b * 9 + 3 * c + k) * 256 + (h1 + p0)) * 256 + w1]);
            v[k][p0] = __ldg(ptr);
        }
    }

    float o16[4][4];
#pragma unroll
    for (int p0 = 0; p0 < 2; p0++) {
#pragma unroll
        for (int q0 = 0; q0 < 2; q0++) {
            const float a2  = cur[p0][q0];
            const float lh1 = 2.0f * (q0 == 0 ? v[0][p0].x : v[0][p0].y) - 1.0f;
            const float hl1 = 2.0f * (q0 == 0 ? v[1][p0].x : v[1][p0].y) - 1.0f;
            const float hh1 = 2.0f * (q0 == 0 ? v[2][p0].x : v[2][p0].y) - 1.0f;
            o16[2 * p0 + 0][2 * q0 + 0] = 0.5f * (a2 - lh1 - hl1 + hh1);
            o16[2 * p0 + 0][2 * q0 + 1] = 0.5f * (a2 - lh1 + hl1 - hh1);
            o16[2 * p0 + 1][2 * q0 + 0] = 0.5f * (a2 + lh1 - hl1 - hh1);
            o16[2 * p0 + 1][2 * q0 + 1] = 0.5f * (a2 + lh1 + hl1 + hh1);
        }
    }

#pragma unroll
    for (int r = 0; r < 4; r++) {
        float4 row;
        row.x = o16[r][0]; row.y = o16[r][1];
        row.z = o16[r][2]; row.w = o16[r][3];
        *reinterpret_cast<float4*>(
            &out[((long)z * 512 + (4 * h0 + r)) * 512 + 4 * w0]) = row;
    }
}

// ---------------------------------------------------------------------------
extern "C" void kernel_launch(void* const* d_in, const int* in_sizes, int n_in,
                              void* d_out, int out_size)
{
    const float* fused  = (const float*)d_in[0];
    const float* hf1    = (const float*)d_in[1];
    const float* hf2    = (const float*)d_in[2];
    const float* conv_w = (const float*)d_in[3];
    const float* conv_b = (const float*)d_in[4];
    float* out = (float*)d_out;

    dim3 cb(32, 4);
    dim3 cg(HH / 4, NB, KSPLIT);            // (32,16,2) = 1024 CTAs
    conv_part_kernel<<<cg, cb>>>(fused, conv_w);

    dim3 ib(128, 2);
    dim3 ig(HH / 2, NB * 3);                // (64,48) = 3072 CTAs
    iwt2_kernel<<<ib.x ? ig : ig, ib>>>(hf1, hf2, conv_b, out);
}

// round 9
// speedup vs baseline: 1.2891x; 1.2891x over previous
#include <cuda_runtime.h>

// ---------------------------------------------------------------------------
// DecoderBlock: conv3x3(64->3) + bias + tanh  -> ll [16,3,128,128]
// then two fused inverse Haar levels          -> out [16,3,512,512]
//
// R9: R7 split-K conv, register-dieted (single input buffer, per-o weight
//     loads) to raise resident warps/SM. Combine+bias+tanh fused in iwt2.
// ---------------------------------------------------------------------------

#define NB   16
#define CIN  64
#define KSPLIT 2
#define KCH  (CIN / KSPLIT)     // 32 channels per CTA
#define HH   128
#define WW   128
#define HW   (HH * WW)

// partial conv sums: [kslice][b][o][h][w] = 2 * 3 MB
__device__ float g_part[KSPLIT * NB * 3 * HW];

__device__ __forceinline__ void stcs4(float* p, float4 v) {
    asm volatile("st.global.cs.v4.f32 [%0], {%1,%2,%3,%4};"
                 :: "l"(p), "f"(v.x), "f"(v.y), "f"(v.z), "f"(v.w));
}

// ---------------------------------------------------------------------------
// Kernel A: streaming conv 3x3 pad1, split-K partial sums.
// Thread = 1 row x 4 cols x 3 outch. CTA (32,4) = 128 threads covers a
// 128-wide x 4-row band. Grid (32,16,2) = 1024 CTAs.
// Register diet: single x[3][6] buffer; weights loaded 3x float4 per outch
// from 16B-aligned smem layout [c][o][12].
// ---------------------------------------------------------------------------
__global__ __launch_bounds__(128) void conv_part_kernel(
    const float* __restrict__ fused,
    const float* __restrict__ conv_w)
{
    __shared__ float s_w[KCH * 36];           // 4608 B, [c][o*12 + t]

    const int tx  = threadIdx.x;              // 0..31 -> cols 4tx..4tx+3
    const int ty  = threadIdx.y;              // 0..3
    const int tid = ty * 32 + tx;
    const int b   = blockIdx.y;
    const int ks  = blockIdx.z;               // k-slice 0/1
    const int kbase = ks * KCH;
    const int gy  = blockIdx.x * 4 + ty;      // output row 0..127

    // stage weights: s_w[c*36 + o*12 + t] (src layout [o][cin][3][3])
    for (int i = tid; i < KCH * 27; i += 128) {
        int c = i / 27, r = i % 27;
        s_w[c * 36 + (r / 9) * 12 + (r % 9)] =
            conv_w[(r / 9) * (CIN * 9) + (kbase + c) * 9 + (r % 9)];
    }
    __syncthreads();

    const bool vtop = (gy > 0);
    const bool vbot = (gy < HH - 1);
    const bool vl   = (tx > 0);
    const bool vr   = (tx < 31);
    const float* p0 = fused + (long)b * CIN * HW + (long)kbase * HW
                            + (gy - 1) * WW + 4 * tx;

    float acc[3][4];
#pragma unroll
    for (int o = 0; o < 3; o++)
#pragma unroll
        for (int q = 0; q < 4; q++) acc[o][q] = 0.0f;

#pragma unroll 1
    for (int c = 0; c < KCH; c++) {
        // load 3x6 input patch for channel c (aligned float4 + 2 halo)
        float x[3][6];
        {
            const bool rv[3] = { vtop, true, vbot };
#pragma unroll
            for (int k = 0; k < 3; k++) {
                const float* rp = p0 + c * HW + k * WW;
                float4 m = make_float4(0.f, 0.f, 0.f, 0.f);
                float l = 0.f, r = 0.f;
                if (rv[k]) {
                    m = __ldg(reinterpret_cast<const float4*>(rp));
                    if (vl) l = __ldg(rp - 1);
                    if (vr) r = __ldg(rp + 4);
                }
                x[k][0] = l;   x[k][1] = m.x; x[k][2] = m.y;
                x[k][3] = m.z; x[k][4] = m.w; x[k][5] = r;
            }
        }

#pragma unroll
        for (int o = 0; o < 3; o++) {
            // 9 weights via 3 aligned LDS.128 (broadcast), short-lived regs
            const float* wb = &s_w[c * 36 + o * 12];
            float4 wa = *reinterpret_cast<const float4*>(wb);
            float4 wm = *reinterpret_cast<const float4*>(wb + 4);
            float4 wz = *reinterpret_cast<const float4*>(wb + 8);
            const float w[9] = { wa.x, wa.y, wa.z, wa.w,
                                 wm.x, wm.y, wm.z, wm.w, wz.x };
#pragma unroll
            for (int ky = 0; ky < 3; ky++)
#pragma unroll
                for (int kx = 0; kx < 3; kx++) {
                    const float wv = w[ky * 3 + kx];
#pragma unroll
                    for (int q = 0; q < 4; q++)
                        acc[o][q] += wv * x[ky][q + kx];
                }
        }
    }

    // raw partial sums, one float4 per out channel (default st: read by iwt2)
    float* pp = &g_part[(long)ks * NB * 3 * HW];
#pragma unroll
    for (int o = 0; o < 3; o++) {
        float4 v;
        v.x = acc[o][0]; v.y = acc[o][1]; v.z = acc[o][2]; v.w = acc[o][3];
        *reinterpret_cast<float4*>(
            &pp[((b * 3 + o) * HH + gy) * WW + 4 * tx]) = v;
    }
}

// ---------------------------------------------------------------------------
// Kernel B: combine(partials)+bias+tanh fused with double inverse Haar.
// One thread per coarse pixel; output stores use .cs (write-once, 50 MB).
// ---------------------------------------------------------------------------
__global__ __launch_bounds__(256) void iwt2_kernel(
    const float* __restrict__ hf1,
    const float* __restrict__ hf2,
    const float* __restrict__ conv_b,
    float* __restrict__ out)
{
    const int w0 = threadIdx.x;                        // 0..127
    const int h0 = blockIdx.x * 2 + threadIdx.y;       // 0..127
    const int z  = blockIdx.y;                         // b*3 + c
    const int b  = z / 3;
    const int c  = z - b * 3;

    const int llidx = (z * HH + h0) * WW + w0;
    const float a = tanhf(g_part[llidx] + g_part[NB * 3 * HW + llidx]
                          + __ldg(&conv_b[c]));

    const int hf2base = ((b * 9 + 3 * c) * HH + h0) * WW + w0;
    const float lh = 2.0f * __ldg(&hf2[hf2base            ]) - 1.0f;
    const float hl = 2.0f * __ldg(&hf2[hf2base + HH * WW  ]) - 1.0f;
    const float hh = 2.0f * __ldg(&hf2[hf2base + 2*HH*WW  ]) - 1.0f;

    float cur[2][2];
    cur[0][0] = 0.5f * (a - lh - hl + hh);
    cur[0][1] = 0.5f * (a - lh + hl - hh);
    cur[1][0] = 0.5f * (a + lh - hl - hh);
    cur[1][1] = 0.5f * (a + lh + hl + hh);

    const int h1 = 2 * h0;
    const int w1 = 2 * w0;
    float2 v[3][2];
#pragma unroll
    for (int k = 0; k < 3; k++) {
#pragma unroll
        for (int p0 = 0; p0 < 2; p0++) {
            const float2* ptr = reinterpret_cast<const float2*>(
                &hf1[((b * 9 + 3 * c + k) * 256 + (h1 + p0)) * 256 + w1]);
            v[k][p0] = __ldg(ptr);
        }
    }

    float o16[4][4];
#pragma unroll
    for (int p0 = 0; p0 < 2; p0++) {
#pragma unroll
        for (int q0 = 0; q0 < 2; q0++) {
            const float a2  = cur[p0][q0];
            const float lh1 = 2.0f * (q0 == 0 ? v[0][p0].x : v[0][p0].y) - 1.0f;
            const float hl1 = 2.0f * (q0 == 0 ? v[1][p0].x : v[1][p0].y) - 1.0f;
            const float hh1 = 2.0f * (q0 == 0 ? v[2][p0].x : v[2][p0].y) - 1.0f;
            o16[2 * p0 + 0][2 * q0 + 0] = 0.5f * (a2 - lh1 - hl1 + hh1);
            o16[2 * p0 + 0][2 * q0 + 1] = 0.5f * (a2 - lh1 + hl1 - hh1);
            o16[2 * p0 + 1][2 * q0 + 0] = 0.5f * (a2 + lh1 - hl1 - hh1);
            o16[2 * p0 + 1][2 * q0 + 1] = 0.5f * (a2 + lh1 + hl1 + hh1);
        }
    }

#pragma unroll
    for (int r = 0; r < 4; r++) {
        float4 row;
        row.x = o16[r][0]; row.y = o16[r][1];
        row.z = o16[r][2]; row.w = o16[r][3];
        stcs4(&out[((long)z * 512 + (4 * h0 + r)) * 512 + 4 * w0], row);
    }
}

// ---------------------------------------------------------------------------
extern "C" void kernel_launch(void* const* d_in, const int* in_sizes, int n_in,
                              void* d_out, int out_size)
{
    const float* fused  = (const float*)d_in[0];
    const float* hf1    = (const float*)d_in[1];
    const float* hf2    = (const float*)d_in[2];
    const float* conv_w = (const float*)d_in[3];
    const float* conv_b = (const float*)d_in[4];
    float* out = (float*)d_out;

    dim3 cb(32, 4);
    dim3 cg(HH / 4, NB, KSPLIT);            // (32,16,2) = 1024 CTAs
    conv_part_kernel<<<cg, cb>>>(fused, conv_w);

    dim3 ib(128, 2);
    dim3 ig(HH / 2, NB * 3);                // (64,48) = 3072 CTAs
    iwt2_kernel<<<ig, ib>>>(hf1, hf2, conv_b, out);
}

// round 10
// speedup vs baseline: 1.4545x; 1.1283x over previous
#include <cuda_runtime.h>

// ---------------------------------------------------------------------------
// DecoderBlock: conv3x3(64->3) + bias + tanh  -> ll [16,3,128,128]
// then two fused inverse Haar levels          -> out [16,3,512,512]
//
// R10: R7 split-K conv + warp-shuffle halo exchange (9 LDG -> 3 LDG + 6 SHFL
//      per channel). Combine+bias+tanh fused in iwt2; output stores .cs.
// ---------------------------------------------------------------------------

#define NB   16
#define CIN  64
#define KSPLIT 2
#define KCH  (CIN / KSPLIT)     // 32 channels per CTA
#define HH   128
#define WW   128
#define HW   (HH * WW)

// partial conv sums: [kslice][b][o][h][w] = 2 * 3 MB
__device__ float g_part[KSPLIT * NB * 3 * HW];

__device__ __forceinline__ void stcs4(float* p, float4 v) {
    asm volatile("st.global.cs.v4.f32 [%0], {%1,%2,%3,%4};"
                 :: "l"(p), "f"(v.x), "f"(v.y), "f"(v.z), "f"(v.w));
}

// ---------------------------------------------------------------------------
// Kernel A: streaming conv 3x3 pad1, split-K partial sums.
// Thread = 1 row x 4 cols x 3 outch. CTA (32,4) = 128 threads; each warp is
// one output row, lanes = contiguous col quads -> halo via shfl.
// Grid (32,16,2) = 1024 CTAs.
// ---------------------------------------------------------------------------
__global__ __launch_bounds__(128) void conv_part_kernel(
    const float* __restrict__ fused,
    const float* __restrict__ conv_w)
{
    __shared__ float s_w[KCH * 32];   // 4 KB, [c][o*9+t] padded to 32

    const int tx  = threadIdx.x;              // lane 0..31 -> cols 4tx..4tx+3
    const int ty  = threadIdx.y;              // 0..3
    const int tid = ty * 32 + tx;
    const int b   = blockIdx.y;
    const int ks  = blockIdx.z;               // k-slice 0/1
    const int kbase = ks * KCH;
    const int gy  = blockIdx.x * 4 + ty;      // output row 0..127

    // stage this slice's weights: s_w[c*32 + o*9 + t] (src [o][cin][3][3])
    for (int i = tid; i < KCH * 27; i += 128) {
        int c = i / 27, r = i % 27;
        s_w[c * 32 + r] =
            conv_w[(r / 9) * (CIN * 9) + (kbase + c) * 9 + (r % 9)];
    }
    __syncthreads();

    const bool vtop = (gy > 0);
    const bool vbot = (gy < HH - 1);
    const bool vl   = (tx > 0);
    const bool vr   = (tx < 31);
    const float* p0 = fused + (long)b * CIN * HW + (long)kbase * HW
                            + (gy - 1) * WW + 4 * tx;

    float x0[3][6], x1[3][6];

    // load 3x6 patch: one aligned float4 per row, halo via warp shuffle
    auto loadch = [&](int c, float (&x)[3][6]) {
        const bool rv[3] = { vtop, true, vbot };
#pragma unroll
        for (int k = 0; k < 3; k++) {
            const float* rp = p0 + c * HW + k * WW;
            float4 m = make_float4(0.f, 0.f, 0.f, 0.f);
            if (rv[k]) m = __ldg(reinterpret_cast<const float4*>(rp));
            float l = __shfl_up_sync(0xffffffffu, m.w, 1);
            float r = __shfl_down_sync(0xffffffffu, m.x, 1);
            x[k][0] = vl ? l : 0.0f;
            x[k][1] = m.x; x[k][2] = m.y; x[k][3] = m.z; x[k][4] = m.w;
            x[k][5] = vr ? r : 0.0f;
        }
    };

    float acc[3][4];
#pragma unroll
    for (int o = 0; o < 3; o++)
#pragma unroll
        for (int q = 0; q < 4; q++) acc[o][q] = 0.0f;

    auto compute = [&](int c, float (&x)[3][6]) {
        float4 w4[8];
#pragma unroll
        for (int k = 0; k < 8; k++)
            w4[k] = *reinterpret_cast<const float4*>(&s_w[c * 32 + 4 * k]);
        const float* w = reinterpret_cast<const float*>(w4);
#pragma unroll
        for (int o = 0; o < 3; o++)
#pragma unroll
            for (int ky = 0; ky < 3; ky++)
#pragma unroll
                for (int kx = 0; kx < 3; kx++) {
                    const float wv = w[o * 9 + ky * 3 + kx];
#pragma unroll
                    for (int q = 0; q < 4; q++)
                        acc[o][q] += wv * x[ky][q + kx];
                }
    };

    loadch(0, x0);
#pragma unroll 1
    for (int c = 0; c < KCH; c += 2) {
        loadch(c + 1, x1);
        compute(c, x0);
        if (c + 2 < KCH) loadch(c + 2, x0);
        compute(c + 1, x1);
    }

    // raw partial sums, one float4 per out channel
    float* pp = &g_part[(long)ks * NB * 3 * HW];
#pragma unroll
    for (int o = 0; o < 3; o++) {
        float4 v;
        v.x = acc[o][0]; v.y = acc[o][1]; v.z = acc[o][2]; v.w = acc[o][3];
        *reinterpret_cast<float4*>(
            &pp[((b * 3 + o) * HH + gy) * WW + 4 * tx]) = v;
    }
}

// ---------------------------------------------------------------------------
// Kernel B: combine(partials)+bias+tanh fused with double inverse Haar.
// One thread per coarse pixel; output stores use .cs (write-once, 50 MB).
// ---------------------------------------------------------------------------
__global__ __launch_bounds__(256) void iwt2_kernel(
    const float* __restrict__ hf1,
    const float* __restrict__ hf2,
    const float* __restrict__ conv_b,
    float* __restrict__ out)
{
    const int w0 = threadIdx.x;                        // 0..127
    const int h0 = blockIdx.x * 2 + threadIdx.y;       // 0..127
    const int z  = blockIdx.y;                         // b*3 + c
    const int b  = z / 3;
    const int c  = z - b * 3;

    const int llidx = (z * HH + h0) * WW + w0;
    const float a = tanhf(g_part[llidx] + g_part[NB * 3 * HW + llidx]
                          + __ldg(&conv_b[c]));

    const int hf2base = ((b * 9 + 3 * c) * HH + h0) * WW + w0;
    const float lh = 2.0f * __ldg(&hf2[hf2base            ]) - 1.0f;
    const float hl = 2.0f * __ldg(&hf2[hf2base + HH * WW  ]) - 1.0f;
    const float hh = 2.0f * __ldg(&hf2[hf2base + 2*HH*WW  ]) - 1.0f;

    float cur[2][2];
    cur[0][0] = 0.5f * (a - lh - hl + hh);
    cur[0][1] = 0.5f * (a - lh + hl - hh);
    cur[1][0] = 0.5f * (a + lh - hl - hh);
    cur[1][1] = 0.5f * (a + lh + hl + hh);

    const int h1 = 2 * h0;
    const int w1 = 2 * w0;
    float2 v[3][2];
#pragma unroll
    for (int k = 0; k < 3; k++) {
#pragma unroll
        for (int p0 = 0; p0 < 2; p0++) {
            const float2* ptr = reinterpret_cast<const float2*>(
                &hf1[((b * 9 + 3 * c + k) * 256 + (h1 + p0)) * 256 + w1]);
            v[k][p0] = __ldg(ptr);
        }
    }

    float o16[4][4];
#pragma unroll
    for (int p0 = 0; p0 < 2; p0++) {
#pragma unroll
        for (int q0 = 0; q0 < 2; q0++) {
            const float a2  = cur[p0][q0];
            const float lh1 = 2.0f * (q0 == 0 ? v[0][p0].x : v[0][p0].y) - 1.0f;
            const float hl1 = 2.0f * (q0 == 0 ? v[1][p0].x : v[1][p0].y) - 1.0f;
            const float hh1 = 2.0f * (q0 == 0 ? v[2][p0].x : v[2][p0].y) - 1.0f;
            o16[2 * p0 + 0][2 * q0 + 0] = 0.5f * (a2 - lh1 - hl1 + hh1);
            o16[2 * p0 + 0][2 * q0 + 1] = 0.5f * (a2 - lh1 + hl1 - hh1);
            o16[2 * p0 + 1][2 * q0 + 0] = 0.5f * (a2 + lh1 - hl1 - hh1);
            o16[2 * p0 + 1][2 * q0 + 1] = 0.5f * (a2 + lh1 + hl1 + hh1);
        }
    }

#pragma unroll
    for (int r = 0; r < 4; r++) {
        float4 row;
        row.x = o16[r][0]; row.y = o16[r][1];
        row.z = o16[r][2]; row.w = o16[r][3];
        stcs4(&out[((long)z * 512 + (4 * h0 + r)) * 512 + 4 * w0], row);
    }
}

// ---------------------------------------------------------------------------
extern "C" void kernel_launch(void* const* d_in, const int* in_sizes, int n_in,
                              void* d_out, int out_size)
{
    const float* fused  = (const float*)d_in[0];
    const float* hf1    = (const float*)d_in[1];
    const float* hf2    = (const float*)d_in[2];
    const float* conv_w = (const float*)d_in[3];
    const float* conv_b = (const float*)d_in[4];
    float* out = (float*)d_out;

    dim3 cb(32, 4);
    dim3 cg(HH / 4, NB, KSPLIT);            // (32,16,2) = 1024 CTAs
    conv_part_kernel<<<cg, cb>>>(fused, conv_w);

    dim3 ib(128, 2);
    dim3 ig(HH / 2, NB * 3);                // (64,48) = 3072 CTAs
    iwt2_kernel<<<ig, ib>>>(hf1, hf2, conv_b, out);
}